// round 8
// baseline (speedup 1.0000x reference)
#include <cuda_runtime.h>

#define NPOS 2304          // 48*48
#define PPAD 2916          // 54*54
typedef unsigned long long ull;

// Scratch (device globals; no runtime allocation)
__device__ float Qbuf[2 * 4 * 2304 * 64];   // [b][g][p][c64]
__device__ float Kbuf[2 * 8 * 2916 * 32];   // [b][SL][padded pos][c32]  (borders never read)
__device__ float Vbuf[2 * 4 * 2916 * 64];   // [b][g][padded pos][c64]  (borders never read)

// ---------------------------------------------------------------------------
// f32x2 helpers
// ---------------------------------------------------------------------------
__device__ __forceinline__ ull dup2(float a) {
    ull r; asm("mov.b64 %0, {%1, %1};" : "=l"(r) : "f"(a)); return r;
}
__device__ __forceinline__ void fma2(ull& d, ull a, ull b) {
    asm("fma.rn.f32x2 %0, %1, %2, %0;" : "+l"(d) : "l"(a), "l"(b));
}

// ---------------------------------------------------------------------------
// Kernel 1: 1x1 conv GEMM (per batch), FFMA2, conflict-free smem, pipelined.
// Tile 128(o) x 64(n), 256 threads, microtile 8(o, f32x2 pairs) x 4(n).
// ---------------------------------------------------------------------------
__global__ __launch_bounds__(256, 3) void conv_kernel(const float* __restrict__ x,
                                                      const float* __restrict__ w,
                                                      const int b) {
    __shared__ float As[16][128];   // [k][o]
    __shared__ float Bs[16][64];    // [k][n]

    const int o0 = blockIdx.y * 128;
    const int n0 = blockIdx.x * 64;
    const int t  = threadIdx.x;
    const int ty = t & 15;      // o quad index
    const int tx = t >> 4;      // n quad index

    const float* Xb = x + b * (256 * NPOS);

    ull acc[4][4];
#pragma unroll
    for (int i = 0; i < 4; i++)
#pragma unroll
        for (int j = 0; j < 4; j++) acc[i][j] = 0ull;

    const int ao0 = t >> 2, akq = t & 3;
    const int ao1 = (t + 256) >> 2;
    const int bkk = t >> 4, bn4 = t & 15;

    float4 av0 = *(const float4*)(w + (o0 + ao0) * 256 + akq * 4);
    float4 av1 = *(const float4*)(w + (o0 + ao1) * 256 + akq * 4);
    float4 bv  = *(const float4*)(Xb + bkk * NPOS + n0 + bn4 * 4);

    for (int c0 = 0; c0 < 256; c0 += 16) {
        __syncthreads();
        As[akq * 4 + 0][ao0] = av0.x;
        As[akq * 4 + 1][ao0] = av0.y;
        As[akq * 4 + 2][ao0] = av0.z;
        As[akq * 4 + 3][ao0] = av0.w;
        As[akq * 4 + 0][ao1] = av1.x;
        As[akq * 4 + 1][ao1] = av1.y;
        As[akq * 4 + 2][ao1] = av1.z;
        As[akq * 4 + 3][ao1] = av1.w;
        *(float4*)&Bs[bkk][bn4 * 4] = bv;
        __syncthreads();

        if (c0 + 16 < 256) {
            av0 = *(const float4*)(w + (o0 + ao0) * 256 + c0 + 16 + akq * 4);
            av1 = *(const float4*)(w + (o0 + ao1) * 256 + c0 + 16 + akq * 4);
            bv  = *(const float4*)(Xb + (c0 + 16 + bkk) * NPOS + n0 + bn4 * 4);
        }

#pragma unroll
        for (int kk = 0; kk < 16; kk++) {
            ull ap[4];
            *(float4*)(&ap[0]) = *(const float4*)&As[kk][ty * 4];
            *(float4*)(&ap[2]) = *(const float4*)&As[kk][64 + ty * 4];
            float bb[4];
            *(float4*)bb = *(const float4*)&Bs[kk][tx * 4];
            ull bd0 = dup2(bb[0]), bd1 = dup2(bb[1]), bd2 = dup2(bb[2]), bd3 = dup2(bb[3]);
#pragma unroll
            for (int op = 0; op < 4; op++) {
                fma2(acc[op][0], ap[op], bd0);
                fma2(acc[op][1], ap[op], bd1);
                fma2(acc[op][2], ap[op], bd2);
                fma2(acc[op][3], ap[op], bd3);
            }
        }
    }

#pragma unroll
    for (int nj = 0; nj < 4; nj++) {
        int hw = n0 + tx * 4 + nj;
        unsigned uhw = (unsigned)hw;
        int i2 = uhw / 48u, j2 = uhw - 48u * i2;
        int pp = (i2 + 3) * 54 + (j2 + 3);
#pragma unroll
        for (int half = 0; half < 2; half++) {
            float2 p0 = *(float2*)&acc[half * 2 + 0][nj];
            float2 p1 = *(float2*)&acc[half * 2 + 1][nj];
            float4 v = make_float4(p0.x, p0.y, p1.x, p1.y);
            int o = o0 + half * 64 + ty * 4;
            if (o < 256) {
                int g = o >> 6;
                *(float4*)&Qbuf[(((b * 4 + g) * 2304 + hw) << 6) + (o & 63)] = v;
            } else if (o < 512) {
                int ok = o - 256;
                int SL = ((ok >> 5) & 1) * 4 + (ok >> 6);
                *(float4*)&Kbuf[(((b * 8 + SL) * PPAD + pp) << 5) + (ok & 31)] = v;
            } else {
                int ov = o - 512;
                *(float4*)&Vbuf[(((b * 4 + (ov >> 6)) * PPAD + pp) << 6) + (ov & 63)] = v;
            }
        }
    }
}

// ---------------------------------------------------------------------------
// Kernel 2: attention (per batch), 2 output rows per block, 768 threads.
// ---------------------------------------------------------------------------
__device__ __forceinline__ float red8(float v) {
    v += __shfl_xor_sync(0xffffffffu, v, 1);
    v += __shfl_xor_sync(0xffffffffu, v, 2);
    v += __shfl_xor_sync(0xffffffffu, v, 4);
    return v;
}
__device__ __forceinline__ float max8(float v) {
    v = fmaxf(v, __shfl_xor_sync(0xffffffffu, v, 1));
    v = fmaxf(v, __shfl_xor_sync(0xffffffffu, v, 2));
    v = fmaxf(v, __shfl_xor_sync(0xffffffffu, v, 4));
    return v;
}
__device__ __forceinline__ float dot4(float4 a, float4 b) {
    return a.x * b.x + a.y * b.y + a.z * b.z + a.w * b.w;
}

#define KT_F4 4320    // 10*54*8
#define VT_F4 6912    // 8*54*16
#define ATT_STRIDE 52

__global__ __launch_bounds__(768, 1) void attn_kernel(const float* __restrict__ rpeh,
                                                      const float* __restrict__ rpew,
                                                      float* __restrict__ out,
                                                      const int b) {
    extern __shared__ float sm[];
    float* Kt   = sm;                        // 17280 floats
    float* Vt   = sm + 17280;                // 27648 floats
    float* atts = Vt + 27648;                // 96*52
    float* rtab = atts + 96 * ATT_STRIDE;    // 96*16

    const int ip0 = blockIdx.x * 2;
    const int g   = blockIdx.y;
    const int t   = threadIdx.x;

    const int s_  = (ip0 >= 24) ? 1 : 0;
    const int SL  = 2 * g + s_;
    const int R0  = 2 * ip0 - 48 * s_;

    const float4 z4 = make_float4(0.f, 0.f, 0.f, 0.f);

    {
        const float4* ks = (const float4*)(Kbuf + (((b * 8 + SL) * PPAD + R0 * 54) << 5));
        float4* kt4 = (float4*)Kt;
        for (int i = t; i < KT_F4; i += 768) {
            unsigned pl = (unsigned)(i >> 3);
            unsigned lr = pl / 54u, col = pl - 54u * lr;
            unsigned grow = (unsigned)R0 + lr;
            bool inter = (grow - 3u) < 48u && (col - 3u) < 48u;
            kt4[i] = inter ? ks[i] : z4;
        }
        const float4* vsrc = (const float4*)(Vbuf + (((b * 4 + g) * PPAD + ip0 * 54) << 6));
        float4* vt4 = (float4*)Vt;
        for (int i = t; i < VT_F4; i += 768) {
            unsigned pl = (unsigned)(i >> 4);
            unsigned lr = pl / 54u, col = pl - 54u * lr;
            unsigned grow = (unsigned)ip0 + lr;
            bool inter = (grow - 3u) < 48u && (col - 3u) < 48u;
            vt4[i] = inter ? vsrc[i] : z4;
        }
    }

    const int rh  = (t >= 384) ? 1 : 0;
    const int tt  = t - rh * 384;
    const int ip  = ip0 + rh;
    const int pos = tt >> 3;
    const int sub = tt & 7;
    const int pidx = rh * 48 + pos;

    const float* qp = Qbuf + (((b * 4 + g) * 2304 + ip * 48 + pos) << 6);
    const float4 qlo = *(const float4*)(qp + 4 * sub);
    const float4 qhi = *(const float4*)(qp + 32 + 4 * sub);

    const bool useH = (SL < 4);
    const float* rp = useH ? (rpeh + SL * 224) : (rpew + (SL - 4) * 224);
    {
        float Rlo[7], Rhi[7];
#pragma unroll
        for (int tq = 0; tq < 7; tq++) {
            float4 rv = *(const float4*)(rp + tq * 32 + 4 * sub);
            Rlo[tq] = red8(dot4(qlo, rv));
            Rhi[tq] = red8(dot4(qhi, rv));
        }
        if (sub == 0) {
#pragma unroll
            for (int tq = 0; tq < 7; tq++) {
                rtab[pidx * 16 + tq]     = Rlo[tq];
                rtab[pidx * 16 + 8 + tq] = Rhi[tq];
            }
        }
    }

    __syncthreads();

    const int rsel = (pos >= 24) ? 1 : 0;
    const int j0 = 2 * pos - 48 * rsel;
    const int krow0 = 2 * rh + rsel;

    float Lreg[7] = {0.f, 0.f, 0.f, 0.f, 0.f, 0.f, 0.f};

    const float4* kt4 = (const float4*)Kt;
#pragma unroll
    for (int k = 0; k < 49; k++) {
        int wA, wB, rA, rB;
        if (k < 24)       { wA = 2 * k;      rA = 0; wB = 2 * k + 1;  rB = 0; }
        else if (k == 24) { wA = 48;         rA = 0; wB = 0;          rB = 1; }
        else              { wA = 2 * k - 49; rA = 1; wB = 2 * k - 48; rB = 1; }
        const int khA = wA / 7, kwA = wA % 7;
        const int khB = wB / 7, kwB = wB % 7;
        float4 va = kt4[(((krow0 + khA) * 54 + j0 + rA + kwA) << 3) + sub];
        float4 vb = kt4[(((krow0 + khB) * 54 + j0 + rB + kwB) << 3) + sub];
        float p = dot4(qlo, va) + dot4(qhi, vb);
        p = red8(p);
        float radd = useH ? (rtab[pidx * 16 + khA] + rtab[pidx * 16 + 8 + khB])
                          : (rtab[pidx * 16 + kwA] + rtab[pidx * 16 + 8 + kwB]);
        float L = p + radd;
        if ((k & 7) == sub) Lreg[k >> 3] = L;
    }

    const int nk = (sub == 0) ? 7 : 6;
    float m = -1e30f;
#pragma unroll
    for (int i = 0; i < 7; i++)
        if (i < nk) m = fmaxf(m, Lreg[i]);
    m = max8(m);
    float ssum = 0.f;
#pragma unroll
    for (int i = 0; i < 7; i++)
        if (i < nk) { Lreg[i] = __expf(Lreg[i] - m); ssum += Lreg[i]; }
    ssum = red8(ssum);
    float inv = 1.0f / ssum;
#pragma unroll
    for (int i = 0; i < 7; i++) {
        int k = sub + 8 * i;
        if (k < 49) atts[pidx * ATT_STRIDE + k] = Lreg[i] * inv;
    }
    __syncwarp();

    ull a0[2] = {0ull, 0ull}, a1[2] = {0ull, 0ull};
    const float4* vt4 = (const float4*)Vt;
#pragma unroll
    for (int k = 0; k < 49; k++) {
        const int kh = k / 7, kw = k % 7;
        float a = atts[pidx * ATT_STRIDE + k];
        ull ad = dup2(a);
        const float4* vv = vt4 + ((((rh + kh) * 54 + pos + kw) << 4) + sub);
        float4 v0 = vv[0];
        float4 v1 = vv[8];
        fma2(a0[0], ad, *(ull*)&v0.x);
        fma2(a0[1], ad, *(ull*)&v0.z);
        fma2(a1[0], ad, *(ull*)&v1.x);
        fma2(a1[1], ad, *(ull*)&v1.z);
    }
    float4 acc0 = *(float4*)&a0[0];
    float4 acc1 = *(float4*)&a1[0];

    float* op = out + (b * 256 + g * 64) * NPOS + ip * 48 + pos;
    op[(4 * sub + 0) * NPOS] = acc0.x;
    op[(4 * sub + 1) * NPOS] = acc0.y;
    op[(4 * sub + 2) * NPOS] = acc0.z;
    op[(4 * sub + 3) * NPOS] = acc0.w;
    op[(32 + 4 * sub + 0) * NPOS] = acc1.x;
    op[(32 + 4 * sub + 1) * NPOS] = acc1.y;
    op[(32 + 4 * sub + 2) * NPOS] = acc1.z;
    op[(32 + 4 * sub + 3) * NPOS] = acc1.w;
}

// ---------------------------------------------------------------------------
// Launch: per-batch split with cross-stream overlap.
//   s0: conv(b0) -> e0 -> conv(b1) ----------------- waitEvent(e1) -> attn(b1)
//   s1:            waitEvent(e0) -> attn(b0) -> e1
// attn(b0) overlaps conv(b1). Stream/events created lazily on the first
// (uncaptured) call; cudaEventRecord / cudaStreamWaitEvent are capture-legal.
// ---------------------------------------------------------------------------
extern "C" void kernel_launch(void* const* d_in, const int* in_sizes, int n_in,
                              void* d_out, int out_size) {
    const float* x  = (const float*)d_in[0];
    const float* w  = (const float*)d_in[1];
    const float* rh = (const float*)d_in[2];
    const float* rw = (const float*)d_in[3];
    float* out = (float*)d_out;

    static cudaStream_t s1 = nullptr;
    static cudaEvent_t e0 = nullptr, e1 = nullptr;
    if (s1 == nullptr) {
        cudaStreamCreateWithFlags(&s1, cudaStreamNonBlocking);
        cudaEventCreateWithFlags(&e0, cudaEventDisableTiming);
        cudaEventCreateWithFlags(&e1, cudaEventDisableTiming);
    }

    const int SMEM = (17280 + 27648 + 96 * ATT_STRIDE + 96 * 16) * 4;
    static bool attr_set = false;
    if (!attr_set) {
        cudaFuncSetAttribute(attn_kernel, cudaFuncAttributeMaxDynamicSharedMemorySize, SMEM);
        attr_set = true;
    }

    dim3 gc(36, 6, 1);   // n=2304/64, o=768/128
    dim3 ga(24, 4, 1);   // 2 rows per block

    // conv for batch 0 on the main (captured) stream
    conv_kernel<<<gc, 256, 0, 0>>>(x, w, 0);
    cudaEventRecord(e0, 0);

    // attn(b0) on side stream, dependent only on conv(b0)
    cudaStreamWaitEvent(s1, e0, 0);
    attn_kernel<<<ga, 768, SMEM, s1>>>(rh, rw, out, 0);
    cudaEventRecord(e1, s1);

    // conv(b1) on main stream (overlaps attn(b0))
    conv_kernel<<<gc, 256, 0, 0>>>(x, w, 1);

    // attn(b1) on main stream after conv(b1) and after attn(b0) joins
    cudaStreamWaitEvent(0, e1, 0);
    attn_kernel<<<ga, 768, SMEM, 0>>>(rh, rw, out, 1);
}

// round 9
// speedup vs baseline: 1.3384x; 1.3384x over previous
#include <cuda_runtime.h>

#define NPOS 2304          // 48*48
#define PPAD 2916          // 54*54
typedef unsigned long long ull;

// Scratch (device globals; no runtime allocation)
__device__ float Qbuf[2 * 4 * 2304 * 64];   // [b][g][p][c64]
__device__ float Kbuf[2 * 8 * 2916 * 32];   // [b][SL][padded pos][c32]  (borders never read)
__device__ float Vbuf[2 * 4 * 2916 * 64];   // [b][g][padded pos][c64]  (borders never read)

// ---------------------------------------------------------------------------
// f32x2 helpers
// ---------------------------------------------------------------------------
__device__ __forceinline__ ull dup2(float a) {
    ull r; asm("mov.b64 %0, {%1, %1};" : "=l"(r) : "f"(a)); return r;
}
__device__ __forceinline__ void fma2(ull& d, ull a, ull b) {
    asm("fma.rn.f32x2 %0, %1, %2, %0;" : "+l"(d) : "l"(a), "l"(b));
}
__device__ __forceinline__ ull add2(ull a, ull b) {
    ull r; asm("add.rn.f32x2 %0, %1, %2;" : "=l"(r) : "l"(a), "l"(b)); return r;
}

// ---------------------------------------------------------------------------
// Kernel 1: 1x1 conv GEMM, FFMA2, conflict-free smem, pipelined (round-6).
// ---------------------------------------------------------------------------
__global__ __launch_bounds__(256, 3) void conv_kernel(const float* __restrict__ x,
                                                      const float* __restrict__ w) {
    __shared__ float As[16][128];   // [k][o]
    __shared__ float Bs[16][64];    // [k][n]

    const int b  = blockIdx.z;
    const int o0 = blockIdx.y * 128;
    const int n0 = blockIdx.x * 64;
    const int t  = threadIdx.x;
    const int ty = t & 15;
    const int tx = t >> 4;

    const float* Xb = x + b * (256 * NPOS);

    ull acc[4][4];
#pragma unroll
    for (int i = 0; i < 4; i++)
#pragma unroll
        for (int j = 0; j < 4; j++) acc[i][j] = 0ull;

    const int ao0 = t >> 2, akq = t & 3;
    const int ao1 = (t + 256) >> 2;
    const int bkk = t >> 4, bn4 = t & 15;

    float4 av0 = *(const float4*)(w + (o0 + ao0) * 256 + akq * 4);
    float4 av1 = *(const float4*)(w + (o0 + ao1) * 256 + akq * 4);
    float4 bv  = *(const float4*)(Xb + bkk * NPOS + n0 + bn4 * 4);

    for (int c0 = 0; c0 < 256; c0 += 16) {
        __syncthreads();
        As[akq * 4 + 0][ao0] = av0.x;
        As[akq * 4 + 1][ao0] = av0.y;
        As[akq * 4 + 2][ao0] = av0.z;
        As[akq * 4 + 3][ao0] = av0.w;
        As[akq * 4 + 0][ao1] = av1.x;
        As[akq * 4 + 1][ao1] = av1.y;
        As[akq * 4 + 2][ao1] = av1.z;
        As[akq * 4 + 3][ao1] = av1.w;
        *(float4*)&Bs[bkk][bn4 * 4] = bv;
        __syncthreads();

        if (c0 + 16 < 256) {
            av0 = *(const float4*)(w + (o0 + ao0) * 256 + c0 + 16 + akq * 4);
            av1 = *(const float4*)(w + (o0 + ao1) * 256 + c0 + 16 + akq * 4);
            bv  = *(const float4*)(Xb + (c0 + 16 + bkk) * NPOS + n0 + bn4 * 4);
        }

#pragma unroll
        for (int kk = 0; kk < 16; kk++) {
            ull ap[4];
            *(float4*)(&ap[0]) = *(const float4*)&As[kk][ty * 4];
            *(float4*)(&ap[2]) = *(const float4*)&As[kk][64 + ty * 4];
            float bb[4];
            *(float4*)bb = *(const float4*)&Bs[kk][tx * 4];
            ull bd0 = dup2(bb[0]), bd1 = dup2(bb[1]), bd2 = dup2(bb[2]), bd3 = dup2(bb[3]);
#pragma unroll
            for (int op = 0; op < 4; op++) {
                fma2(acc[op][0], ap[op], bd0);
                fma2(acc[op][1], ap[op], bd1);
                fma2(acc[op][2], ap[op], bd2);
                fma2(acc[op][3], ap[op], bd3);
            }
        }
    }

#pragma unroll
    for (int nj = 0; nj < 4; nj++) {
        int hw = n0 + tx * 4 + nj;
        unsigned uhw = (unsigned)hw;
        int i2 = uhw / 48u, j2 = uhw - 48u * i2;
        int pp = (i2 + 3) * 54 + (j2 + 3);
#pragma unroll
        for (int half = 0; half < 2; half++) {
            float2 p0 = *(float2*)&acc[half * 2 + 0][nj];
            float2 p1 = *(float2*)&acc[half * 2 + 1][nj];
            float4 v = make_float4(p0.x, p0.y, p1.x, p1.y);
            int o = o0 + half * 64 + ty * 4;
            if (o < 256) {
                int g = o >> 6;
                *(float4*)&Qbuf[(((b * 4 + g) * 2304 + hw) << 6) + (o & 63)] = v;
            } else if (o < 512) {
                int ok = o - 256;
                int SL = ((ok >> 5) & 1) * 4 + (ok >> 6);
                *(float4*)&Kbuf[(((b * 8 + SL) * PPAD + pp) << 5) + (ok & 31)] = v;
            } else {
                int ov = o - 512;
                *(float4*)&Vbuf[(((b * 4 + (ov >> 6)) * PPAD + pp) << 6) + (ov & 63)] = v;
            }
        }
    }
}

// ---------------------------------------------------------------------------
// Kernel 2: attention, 2 rows/block, 768 threads. QK uses smem-transpose
// reduction (no per-k shuffles) and f32x2 dots.
// ---------------------------------------------------------------------------
__device__ __forceinline__ float red8(float v) {
    v += __shfl_xor_sync(0xffffffffu, v, 1);
    v += __shfl_xor_sync(0xffffffffu, v, 2);
    v += __shfl_xor_sync(0xffffffffu, v, 4);
    return v;
}
__device__ __forceinline__ float max8(float v) {
    v = fmaxf(v, __shfl_xor_sync(0xffffffffu, v, 1));
    v = fmaxf(v, __shfl_xor_sync(0xffffffffu, v, 2));
    v = fmaxf(v, __shfl_xor_sync(0xffffffffu, v, 4));
    return v;
}
__device__ __forceinline__ float dot4(float4 a, float4 b) {
    return a.x * b.x + a.y * b.y + a.z * b.z + a.w * b.w;
}

#define KT_F4 4320    // 10*54*8
#define VT_F4 6912    // 8*54*16
#define ATT_STRIDE 50
#define RT_STRIDE 14
#define PART_STRIDE 72
// smem floats: Kt 17280 + Vt 27648 + atts 4800 + rtab 1344 + part 6912 = 57984
#define ATT_SMEM_FLOATS (17280 + 27648 + 96 * ATT_STRIDE + 96 * RT_STRIDE + 96 * PART_STRIDE)

__global__ __launch_bounds__(768, 1) void attn_kernel(const float* __restrict__ rpeh,
                                                      const float* __restrict__ rpew,
                                                      float* __restrict__ out) {
    extern __shared__ float sm[];
    float* Kt    = sm;                          // 17280
    float* Vt    = sm + 17280;                  // 27648
    float* atts  = Vt + 27648;                  // 96*50
    float* rtab  = atts + 96 * ATT_STRIDE;      // 96*14
    float* partb = rtab + 96 * RT_STRIDE;       // 96*72

    const int ip0 = blockIdx.x * 2;
    const int g   = blockIdx.y;
    const int b   = blockIdx.z;
    const int t   = threadIdx.x;

    const int s_  = (ip0 >= 24) ? 1 : 0;
    const int SL  = 2 * g + s_;
    const int R0  = 2 * ip0 - 48 * s_;

    const float4 z4 = make_float4(0.f, 0.f, 0.f, 0.f);

    // ---- stage K rows R0..R0+9 and V rows ip0..ip0+7; zero borders ----
    {
        const float4* ks = (const float4*)(Kbuf + (((b * 8 + SL) * PPAD + R0 * 54) << 5));
        float4* kt4s = (float4*)Kt;
        for (int i = t; i < KT_F4; i += 768) {
            unsigned pl = (unsigned)(i >> 3);
            unsigned lr = pl / 54u, col = pl - 54u * lr;
            unsigned grow = (unsigned)R0 + lr;
            bool inter = (grow - 3u) < 48u && (col - 3u) < 48u;
            kt4s[i] = inter ? ks[i] : z4;
        }
        const float4* vsrc = (const float4*)(Vbuf + (((b * 4 + g) * PPAD + ip0 * 54) << 6));
        float4* vt4s = (float4*)Vt;
        for (int i = t; i < VT_F4; i += 768) {
            unsigned pl = (unsigned)(i >> 4);
            unsigned lr = pl / 54u, col = pl - 54u * lr;
            unsigned grow = (unsigned)ip0 + lr;
            bool inter = (grow - 3u) < 48u && (col - 3u) < 48u;
            vt4s[i] = inter ? vsrc[i] : z4;
        }
    }

    const int rh  = (t >= 384) ? 1 : 0;
    const int tt  = t - rh * 384;
    const int ip  = ip0 + rh;
    const int pos = tt >> 3;
    const int sub = tt & 7;
    const int pidx = rh * 48 + pos;

    const float* qp = Qbuf + (((b * 4 + g) * 2304 + ip * 48 + pos) << 6);
    const float4 qlo = *(const float4*)(qp + 4 * sub);
    const float4 qhi = *(const float4*)(qp + 32 + 4 * sub);
    const ull ql0 = *(const ull*)&qlo.x, ql1 = *(const ull*)&qlo.z;
    const ull qh0 = *(const ull*)&qhi.x, qh1 = *(const ull*)&qhi.z;

    // ---- RPE dot products -> rtab (once; red8 here is amortized) ----
    const bool useH = (SL < 4);
    const float* rp = useH ? (rpeh + SL * 224) : (rpew + (SL - 4) * 224);
    {
        float Rlo[7], Rhi[7];
#pragma unroll
        for (int tq = 0; tq < 7; tq++) {
            float4 rv = *(const float4*)(rp + tq * 32 + 4 * sub);
            Rlo[tq] = red8(dot4(qlo, rv));
            Rhi[tq] = red8(dot4(qhi, rv));
        }
        if (sub == 0) {
#pragma unroll
            for (int tq = 0; tq < 7; tq++) {
                rtab[pidx * RT_STRIDE + tq]     = Rlo[tq];
                rtab[pidx * RT_STRIDE + 7 + tq] = Rhi[tq];
            }
        }
    }

    __syncthreads();

    // ---- per-lane RPE sums for the k's this lane will reduce (k = 8i+sub) ----
    float Radd[7];
#pragma unroll
    for (int i = 0; i < 7; i++) {
        int k = 8 * i + sub;
        int kc = (k > 48) ? 0 : k;
        int wA, wB;
        if (kc < 24)       { wA = 2 * kc;      wB = 2 * kc + 1; }
        else if (kc == 24) { wA = 48;          wB = 0; }
        else               { wA = 2 * kc - 49; wB = 2 * kc - 48; }
        int khA = wA / 7, kwA = wA - 7 * khA;
        int khB = wB / 7, kwB = wB - 7 * khB;
        int idxA = useH ? khA : kwA;
        int idxB = useH ? khB : kwB;
        Radd[i] = rtab[pidx * RT_STRIDE + idxA] + rtab[pidx * RT_STRIDE + 7 + idxB];
    }

    const int rsel = (pos >= 24) ? 1 : 0;
    const int j0 = 2 * pos - 48 * rsel;
    const int krow0 = 2 * rh + rsel;

    const float4* kt4 = (const float4*)Kt;
    const float4* kbase = kt4 + ((krow0 * 54 + j0) << 3) + sub;   // slice sub of cell (krow0, j0)
    float* part = partb + pidx * PART_STRIDE;

    float Lreg[7];
#pragma unroll
    for (int c = 0; c < 7; c++) {
        // compute partials for k = 8c..8c+7 (this lane's 4-ch slices)
#pragma unroll
        for (int kk = 0; kk < 8; kk++) {
            const int k = c * 8 + kk;
            if (k <= 48) {
                int wA, wB, rA, rB;
                if (k < 24)       { wA = 2 * k;      rA = 0; wB = 2 * k + 1;  rB = 0; }
                else if (k == 24) { wA = 48;         rA = 0; wB = 0;          rB = 1; }
                else              { wA = 2 * k - 49; rA = 1; wB = 2 * k - 48; rB = 1; }
                const int khA = wA / 7, kwA = wA % 7;
                const int khB = wB / 7, kwB = wB % 7;
                float4 va = kbase[(khA * 54 + rA + kwA) << 3];
                float4 vb = kbase[(khB * 54 + rB + kwB) << 3];
                ull aA = 0ull, aB = 0ull;
                fma2(aA, *(const ull*)&va.x, ql0);
                fma2(aA, *(const ull*)&va.z, ql1);
                fma2(aB, *(const ull*)&vb.x, qh0);
                fma2(aB, *(const ull*)&vb.z, qh1);
                ull s = add2(aA, aB);
                float2 sf = *(float2*)&s;
                part[kk * 8 + sub] = sf.x + sf.y;
            }
        }
        __syncwarp();
        // reduce k = 8c + sub
        {
            int k = c * 8 + sub;
            if (k <= 48) {
                float4 r0 = *(const float4*)&part[sub * 8];
                float4 r1 = *(const float4*)&part[sub * 8 + 4];
                Lreg[c] = ((r0.x + r0.y) + (r0.z + r0.w)) +
                          ((r1.x + r1.y) + (r1.z + r1.w)) + Radd[c];
            } else {
                Lreg[c] = -1e30f;
            }
        }
        __syncwarp();
    }

    // ---- softmax over 49 (k distributed as 8i+sub across lanes) ----
    const int nk = (sub == 0) ? 7 : 6;
    float m = -1e30f;
#pragma unroll
    for (int i = 0; i < 7; i++)
        if (i < nk) m = fmaxf(m, Lreg[i]);
    m = max8(m);
    float ssum = 0.f;
#pragma unroll
    for (int i = 0; i < 7; i++)
        if (i < nk) { Lreg[i] = __expf(Lreg[i] - m); ssum += Lreg[i]; }
    ssum = red8(ssum);
    float inv = 1.0f / ssum;
#pragma unroll
    for (int i = 0; i < 7; i++) {
        int k = 8 * i + sub;
        if (k < 49) atts[pidx * ATT_STRIDE + k] = Lreg[i] * inv;
    }
    __syncwarp();

    // ---- AV (f32x2): lane accumulates channels {4sub..} and {32+4sub..} ----
    ull a0[2] = {0ull, 0ull}, a1[2] = {0ull, 0ull};
    const float4* vt4 = (const float4*)Vt;
#pragma unroll
    for (int k = 0; k < 49; k++) {
        const int kh = k / 7, kw = k % 7;
        float a = atts[pidx * ATT_STRIDE + k];
        ull ad = dup2(a);
        const float4* vv = vt4 + ((((rh + kh) * 54 + pos + kw) << 4) + sub);
        float4 v0 = vv[0];
        float4 v1 = vv[8];
        fma2(a0[0], ad, *(ull*)&v0.x);
        fma2(a0[1], ad, *(ull*)&v0.z);
        fma2(a1[0], ad, *(ull*)&v1.x);
        fma2(a1[1], ad, *(ull*)&v1.z);
    }
    float4 acc0 = *(float4*)&a0[0];
    float4 acc1 = *(float4*)&a1[0];

    float* op = out + (b * 256 + g * 64) * NPOS + ip * 48 + pos;
    op[(4 * sub + 0) * NPOS] = acc0.x;
    op[(4 * sub + 1) * NPOS] = acc0.y;
    op[(4 * sub + 2) * NPOS] = acc0.z;
    op[(4 * sub + 3) * NPOS] = acc0.w;
    op[(32 + 4 * sub + 0) * NPOS] = acc1.x;
    op[(32 + 4 * sub + 1) * NPOS] = acc1.y;
    op[(32 + 4 * sub + 2) * NPOS] = acc1.z;
    op[(32 + 4 * sub + 3) * NPOS] = acc1.w;
}

// ---------------------------------------------------------------------------
extern "C" void kernel_launch(void* const* d_in, const int* in_sizes, int n_in,
                              void* d_out, int out_size) {
    const float* x  = (const float*)d_in[0];
    const float* w  = (const float*)d_in[1];
    const float* rh = (const float*)d_in[2];
    const float* rw = (const float*)d_in[3];
    float* out = (float*)d_out;

    dim3 gc(36, 6, 2);   // n=2304/64, o=768/128, b
    conv_kernel<<<gc, 256>>>(x, w);

    const int SMEM = ATT_SMEM_FLOATS * 4;
    cudaFuncSetAttribute(attn_kernel, cudaFuncAttributeMaxDynamicSharedMemorySize, SMEM);
    dim3 ga(24, 4, 2);   // 2 rows per block
    attn_kernel<<<ga, 768, SMEM>>>(rh, rw, out);
}